// round 10
// baseline (speedup 1.0000x reference)
#include <cuda_runtime.h>
#include <cuda_bf16.h>
#include <cstdint>
#include <math.h>

#define BATCH 16
#define SEQT  256
#define VOCAB 32000
#define EMBD  200
#define HID   256
#define NT    (BATCH*SEQT)   // 4096 rows
#define G4    (4*HID)        // 1024 gate rows

// ---------------- scratch (static device arrays; no allocation) ----------------
__device__ float g_xg[NT*G4];                               // input projections (fp32)
__device__ __align__(16) __nv_bfloat16 g_hb[NT*HID];        // bf16 activations (layer I/O)
__device__ __align__(16) __nv_bfloat16 g_wb[VOCAB*HID];     // bf16 fcW
__device__ __align__(16) __nv_bfloat16 g_wib0[G4*HID];      // bf16 Wi0 (padded K 200->256)
__device__ __align__(16) __nv_bfloat16 g_wib1[G4*HID];      // bf16 Wi1
__device__ __align__(16) __nv_bfloat16 g_wib2[G4*HID];      // bf16 Wi2

// ---------------- helpers ----------------
__device__ __forceinline__ float sigmoid_f(float x) {
    x = fminf(fmaxf(x, -30.f), 30.f);
    return 1.f / (1.f + __expf(-x));
}
__device__ __forceinline__ float tanh_f(float x) {
    x = fminf(fmaxf(x, -15.f), 15.f);
    float e = __expf(2.f * x);
    return (e - 1.f) / (e + 1.f);
}
__device__ __forceinline__ uint32_t smem_u32(const void* p) {
    uint32_t a;
    asm("{ .reg .u64 t; cvta.to.shared.u64 t, %1; cvt.u32.u64 %0, t; }" : "=r"(a) : "l"(p));
    return a;
}

// ---------------- embedding gather -> bf16, padded to 256 cols ----------------
__global__ void embed_bf(const int* __restrict__ x, const float* __restrict__ emb,
                         __nv_bfloat16* __restrict__ out) {
    int idx = blockIdx.x * blockDim.x + threadIdx.x;
    if (idx < NT * 256) {
        int n = idx >> 8, e = idx & 255;
        float v = (e < EMBD) ? emb[(size_t)x[n] * EMBD + e] : 0.f;
        out[idx] = __float2bfloat16(v);
    }
}

// ---------------- one launch: cast fcW + all three Wi (Wi0 padded 200->256) ----------------
__global__ void cast_all(const float* __restrict__ Wi0, const float* __restrict__ Wi1,
                         const float* __restrict__ Wi2, const float* __restrict__ fcW,
                         __nv_bfloat16* __restrict__ o0, __nv_bfloat16* __restrict__ o1,
                         __nv_bfloat16* __restrict__ o2, __nv_bfloat16* __restrict__ ow) {
    int idx = blockIdx.x * blockDim.x + threadIdx.x;
    if (idx < VOCAB * 256) ow[idx] = __float2bfloat16(fcW[idx]);
    if (idx < G4 * 256) {
        int r = idx >> 8, c = idx & 255;
        o0[idx] = __float2bfloat16(c < EMBD ? Wi0[(size_t)r * EMBD + c] : 0.f);
        o1[idx] = __float2bfloat16(Wi1[idx]);
        o2[idx] = __float2bfloat16(Wi2[idx]);
    }
}

// ---------------- mma/ldmatrix primitives ----------------
__device__ __forceinline__ void ldsm_x4(uint32_t addr, uint32_t& r0, uint32_t& r1,
                                        uint32_t& r2, uint32_t& r3) {
    asm volatile("ldmatrix.sync.aligned.m8n8.x4.shared.b16 {%0,%1,%2,%3}, [%4];"
                 : "=r"(r0), "=r"(r1), "=r"(r2), "=r"(r3) : "r"(addr));
}
__device__ __forceinline__ void mma16816(float* c, const uint32_t* a, const uint32_t* b) {
    asm volatile("mma.sync.aligned.m16n8k16.row.col.f32.bf16.bf16.f32 "
                 "{%0,%1,%2,%3}, {%4,%5,%6,%7}, {%8,%9}, {%0,%1,%2,%3};"
                 : "+f"(c[0]), "+f"(c[1]), "+f"(c[2]), "+f"(c[3])
                 : "r"(a[0]), "r"(a[1]), "r"(a[2]), "r"(a[3]), "r"(b[0]), "r"(b[1]));
}

// ---------------- bf16 GEMM via warp mma.sync: out[M,N] = A @ B^T + bias ----------------
#define MMA_SMEM_BYTES (128*512*2)

__global__ __launch_bounds__(256, 1) void gemm_bf16(
    const __nv_bfloat16* __restrict__ Ab,
    const __nv_bfloat16* __restrict__ Bb,
    const float* __restrict__ bias,
    float* __restrict__ out,
    int Ncols)
{
    extern __shared__ __align__(128) unsigned char smem[];
    const uint32_t sbase = smem_u32(smem);
    const uint32_t sA = sbase;
    const uint32_t sB = sbase + 65536;

    const int tid = threadIdx.x;
    const int wid = tid >> 5;
    const int lid = tid & 31;
    const int row0 = blockIdx.x * 128;
    const int col0 = blockIdx.y * 128;

#pragma unroll
    for (int i = 0; i < 16; i++) {
        int idx = tid + i * 256;
        int r = idx >> 5, c = idx & 31;
        uint32_t soff = (uint32_t)r * 512u + (uint32_t)((c ^ (r & 7)) << 4);
        *(uint4*)(smem + soff) = *(const uint4*)(Ab + (size_t)(row0 + r) * HID + (c << 3));
        *(uint4*)(smem + 65536 + soff) = *(const uint4*)(Bb + (size_t)(col0 + r) * HID + (c << 3));
    }
    __syncthreads();

    const int mw = (wid & 1) * 64;
    const int nw = (wid >> 1) * 32;

    float c[4][4][4];
#pragma unroll
    for (int mi = 0; mi < 4; mi++)
#pragma unroll
        for (int ni = 0; ni < 4; ni++)
#pragma unroll
            for (int e = 0; e < 4; e++) c[mi][ni][e] = 0.f;

#pragma unroll
    for (int ks = 0; ks < 16; ks++) {
        uint32_t a[4][4];
#pragma unroll
        for (int mi = 0; mi < 4; mi++) {
            int r = mw + mi * 16 + (lid & 15);
            int chunk = ks * 2 + (lid >> 4);
            uint32_t addr = sA + (uint32_t)r * 512u + (uint32_t)((chunk ^ (r & 7)) << 4);
            ldsm_x4(addr, a[mi][0], a[mi][1], a[mi][2], a[mi][3]);
        }
        uint32_t b[4][2];
#pragma unroll
        for (int nb = 0; nb < 2; nb++) {
            int n = nw + nb * 16 + (lid & 7) + ((lid & 16) ? 8 : 0);
            int chunk = ks * 2 + ((lid & 8) ? 1 : 0);
            uint32_t addr = sB + (uint32_t)n * 512u + (uint32_t)((chunk ^ (n & 7)) << 4);
            uint32_t r0, r1, r2, r3;
            ldsm_x4(addr, r0, r1, r2, r3);
            b[nb * 2 + 0][0] = r0; b[nb * 2 + 0][1] = r1;
            b[nb * 2 + 1][0] = r2; b[nb * 2 + 1][1] = r3;
        }
#pragma unroll
        for (int mi = 0; mi < 4; mi++)
#pragma unroll
            for (int ni = 0; ni < 4; ni++)
                mma16816(c[mi][ni], a[mi], b[ni]);
    }

#pragma unroll
    for (int mi = 0; mi < 4; mi++) {
        int r = row0 + mw + mi * 16 + (lid >> 2);
#pragma unroll
        for (int ni = 0; ni < 4; ni++) {
            int col = col0 + nw + ni * 8 + (lid & 3) * 2;
            float2 bv = *(const float2*)&bias[col];
            float2 v0 = make_float2(c[mi][ni][0] + bv.x, c[mi][ni][1] + bv.y);
            float2 v1 = make_float2(c[mi][ni][2] + bv.x, c[mi][ni][3] + bv.y);
            *(float2*)&out[(size_t)r * Ncols + col] = v0;
            *(float2*)&out[(size_t)(r + 8) * Ncols + col] = v1;
        }
    }
}

// ---------------- LSTM recurrence: ONE 8-CTA cluster, all 16 batches, tensor-core gates ----
// CTA 'rank' owns hidden units j in [rank*32, rank*32+32) (gate rows q*256+rank*32+j).
// Per step: gates[128,16] = Whb[128,256] @ h[16,256]^T via mma.sync (A-frags preloaded in regs),
// activations on 256 threads, h slice (16x32 bf16, 80B pitch block = 1280B) bulk-copied to 7 peers.
#define SM_WHB   0                 // Whb [128][256] bf16, pitch 512B = 64KB
#define SM_HB    65536             // hB[2 bufs][8 kblocks][16 n][80B] = 2*10240
#define SM_GATES 86016             // gates [128][18] f32 = 9216
#define SM_MBAR  95232             // mbar[2]
#define REC_SMEM 95360

__global__ void __cluster_dims__(8, 1, 1) __launch_bounds__(256, 1)
lstm_rec_mma(const float* __restrict__ xg, const float* __restrict__ Wh,
             __nv_bfloat16* __restrict__ hout)
{
    extern __shared__ __align__(128) unsigned char smem[];
    uint32_t rank;
    asm("mov.u32 %0, %%cluster_ctarank;" : "=r"(rank));
    const int tid = threadIdx.x;
    const int wid = tid >> 5;
    const int lid = tid & 31;
    const uint32_t sbase = smem_u32(smem);
    const uint32_t sWhb = sbase + SM_WHB;
    const uint32_t sHB  = sbase + SM_HB;
    float* gatesF = (float*)(smem + SM_GATES);
    const uint32_t mbar_base = sbase + SM_MBAR;

    // ---- load Whb: local row lr=q*32+j <- global gate row q*256+rank*32+j, bf16 cast
    for (int i = tid; i < 128 * 64; i += 256) {
        int lr = i >> 6, cc = (i & 63) << 2;       // cc: col in floats (multiple of 4)
        int q = lr >> 5, j = lr & 31;
        float4 v = *(const float4*)&Wh[(size_t)(q * 256 + (int)rank * 32 + j) * 256 + cc];
        __nv_bfloat162 p0 = __floats2bfloat162_rn(v.x, v.y);
        __nv_bfloat162 p1 = __floats2bfloat162_rn(v.z, v.w);
        *(uint2*)(smem + SM_WHB + lr * 512 + cc * 2) =
            make_uint2(*(uint32_t*)&p0, *(uint32_t*)&p1);
    }
    // zero both h buffers
    for (int i = tid; i < (2 * 10240) / 4; i += 256)
        ((uint32_t*)(smem + SM_HB))[i] = 0u;
    if (tid == 0) {
        asm volatile("mbarrier.init.shared.b64 [%0], %1;" :: "r"(mbar_base), "r"(1u) : "memory");
        asm volatile("mbarrier.init.shared.b64 [%0], %1;" :: "r"(mbar_base + 8), "r"(1u) : "memory");
        asm volatile("mbarrier.arrive.expect_tx.shared.b64 _, [%0], %1;" :: "r"(mbar_base), "r"(8960u) : "memory");
        asm volatile("mbarrier.arrive.expect_tx.shared.b64 _, [%0], %1;" :: "r"(mbar_base + 8), "r"(8960u) : "memory");
    }
    __syncthreads();

    // ---- preload A fragments (warp w owns local rows [16w,16w+16), all 16 k-steps)
    uint32_t a[16][4];
#pragma unroll
    for (int ks = 0; ks < 16; ks++) {
        uint32_t addr = sWhb + (uint32_t)((wid << 4) + (lid & 15)) * 512u
                      + (uint32_t)ks * 32u + (uint32_t)((lid >> 4) << 4);
        ldsm_x4(addr, a[ks][0], a[ks][1], a[ks][2], a[ks][3]);
    }

    // one-time cluster barrier: peers' smem init (zeros + armed mbars) visible
    asm volatile("barrier.cluster.arrive.aligned;" ::: "memory");
    asm volatile("barrier.cluster.wait.aligned;" ::: "memory");

    const int j = tid & 31;          // hidden-local
    const int bp = tid >> 5;         // batch pair 0..7
    const int b0 = bp * 2, b1 = b0 + 1;
    float cst0 = 0.f, cst1 = 0.f;    // cell state (fp32, persistent)
    int ph0 = 0, ph1 = 0;

    const uint32_t nsel  = (uint32_t)((lid & 7) + ((lid & 16) ? 8 : 0));
    const uint32_t oct16 = (uint32_t)((lid & 8) ? 16 : 0);

    for (int t = 0; t < SEQT; t++) {
        // prefetch xg for this step (before the wait)
        float xgv0[4], xgv1[4];
#pragma unroll
        for (int q = 0; q < 4; q++) {
            size_t base = ((size_t)(b0 * 256 + t)) * 1024 + q * 256 + rank * 32 + j;
            xgv0[q] = __ldg(&xg[base]);
            xgv1[q] = __ldg(&xg[base + 256 * 1024]);
        }

        const int cb = t & 1;
        if (t > 0) {
            uint32_t mb = mbar_base + (uint32_t)cb * 8u;
            uint32_t par = cb ? ph1 : ph0;
            uint32_t done;
            asm volatile(
                "{\n\t.reg .pred p;\n\t"
                "mbarrier.try_wait.parity.acquire.cluster.shared::cta.b64 p, [%1], %2;\n\t"
                "selp.b32 %0, 1, 0, p;\n\t}"
                : "=r"(done) : "r"(mb), "r"(par) : "memory");
            if (!done) {
                asm volatile(
                    "{\n\t.reg .pred P1;\n\t"
                    "WL_%=: mbarrier.try_wait.parity.acquire.cluster.shared::cta.b64 P1, [%0], %1, 0x989680;\n\t"
                    "@P1 bra.uni WD_%=;\n\tbra.uni WL_%=;\n\tWD_%=:\n\t}"
                    :: "r"(mb), "r"(par) : "memory");
            }
            if (cb) ph1 ^= 1; else ph0 ^= 1;
            if (tid == 0) {   // re-arm for t+2 (safe: peers' next send requires our send below)
                asm volatile("mbarrier.arrive.expect_tx.shared.b64 _, [%0], %1;"
                             :: "r"(mb), "r"(8960u) : "memory");
            }
        }

        // ---- gates = Whb @ h^T  (per warp: 16 rows x 16 batches, K=256)
        float cf0[4] = {0.f, 0.f, 0.f, 0.f};
        float cf1[4] = {0.f, 0.f, 0.f, 0.f};
        const uint32_t hbuf = sHB + (uint32_t)cb * 10240u;
#pragma unroll
        for (int ks = 0; ks < 16; ks++) {
            uint32_t baddr = hbuf + (uint32_t)(ks >> 1) * 1280u + nsel * 80u
                           + (uint32_t)((ks & 1) * 32) + oct16;
            uint32_t r0, r1, r2, r3;
            ldsm_x4(baddr, r0, r1, r2, r3);
            uint32_t bA[2] = {r0, r1};
            uint32_t bB[2] = {r2, r3};
            mma16816(cf0, a[ks], bA);
            mma16816(cf1, a[ks], bB);
        }
        {
            int r = (wid << 4) + (lid >> 2);
            int col = (lid & 3) * 2;
            *(float2*)&gatesF[(size_t)r * 18 + col]           = make_float2(cf0[0], cf0[1]);
            *(float2*)&gatesF[(size_t)(r + 8) * 18 + col]     = make_float2(cf0[2], cf0[3]);
            *(float2*)&gatesF[(size_t)r * 18 + 8 + col]       = make_float2(cf1[0], cf1[1]);
            *(float2*)&gatesF[(size_t)(r + 8) * 18 + 8 + col] = make_float2(cf1[2], cf1[3]);
        }
        __syncthreads();

        // ---- activations: thread -> (hidden j, batches b0,b1)
        float2 gi = *(float2*)&gatesF[(size_t)(0 * 32 + j) * 18 + b0];
        float2 gf = *(float2*)&gatesF[(size_t)(1 * 32 + j) * 18 + b0];
        float2 gg = *(float2*)&gatesF[(size_t)(2 * 32 + j) * 18 + b0];
        float2 go = *(float2*)&gatesF[(size_t)(3 * 32 + j) * 18 + b0];
        float i0 = sigmoid_f(gi.x + xgv0[0]), i1 = sigmoid_f(gi.y + xgv1[0]);
        float f0 = sigmoid_f(gf.x + xgv0[1]), f1 = sigmoid_f(gf.y + xgv1[1]);
        float g0 = tanh_f   (gg.x + xgv0[2]), g1 = tanh_f   (gg.y + xgv1[2]);
        float o0 = sigmoid_f(go.x + xgv0[3]), o1 = sigmoid_f(go.y + xgv1[3]);
        cst0 = f0 * cst0 + i0 * g0;
        cst1 = f1 * cst1 + i1 * g1;
        float h0 = o0 * tanh_f(cst0);
        float h1 = o1 * tanh_f(cst1);

        const int nb = (t + 1) & 1;
        __nv_bfloat16 hb0 = __float2bfloat16(h0);
        __nv_bfloat16 hb1 = __float2bfloat16(h1);
        {   // local h block write: hB[nb][rank][b][j], row pitch 80B (40 bf16)
            __nv_bfloat16* hrow = (__nv_bfloat16*)(smem + SM_HB + nb * 10240 + rank * 1280);
            hrow[b0 * 40 + j] = hb0;
            hrow[b1 * 40 + j] = hb1;
        }
        __syncthreads();   // h block complete + STS drained

        if (t + 1 < SEQT && tid < 8 && tid != (int)rank) {
            asm volatile("fence.proxy.async.shared::cta;" ::: "memory");
            uint32_t src = sHB + (uint32_t)nb * 10240u + rank * 1280u;
            uint32_t lbar = mbar_base + (uint32_t)nb * 8u;
            uint32_t dst, rbar;
            asm("mapa.shared::cluster.u32 %0, %1, %2;" : "=r"(dst) : "r"(src), "r"(tid));
            asm("mapa.shared::cluster.u32 %0, %1, %2;" : "=r"(rbar) : "r"(lbar), "r"(tid));
            asm volatile(
                "cp.async.bulk.shared::cluster.shared::cta.mbarrier::complete_tx::bytes "
                "[%0], [%1], %2, [%3];"
                :: "r"(dst), "r"(src), "r"(1280u), "r"(rbar) : "memory");
        }

        // global h store AFTER the notify (off the critical path)
        hout[(size_t)(b0 * 256 + t) * 256 + rank * 32 + j] = hb0;
        hout[(size_t)(b1 * 256 + t) * 256 + rank * 32 + j] = hb1;
    }
}

// ---------------- online log_softmax (512 threads, float4) ----------------
__global__ __launch_bounds__(512) void logsoftmax_kernel(float* __restrict__ out) {
    const int n = blockIdx.x;
    float4* row4 = (float4*)(out + (size_t)n * VOCAB);
    const int tid = threadIdx.x;
    __shared__ float redm[16], reds[16];
    __shared__ float bcast;

    float m = -1e30f, s = 0.f;
    for (int k = tid; k < VOCAB / 4; k += 512) {
        float4 v = row4[k];
        float vm = fmaxf(fmaxf(v.x, v.y), fmaxf(v.z, v.w));
        float M = fmaxf(m, vm);
        float sc = __expf(m - M);
        s = s * sc + __expf(v.x - M) + __expf(v.y - M) + __expf(v.z - M) + __expf(v.w - M);
        m = M;
    }
#pragma unroll
    for (int o = 16; o; o >>= 1) {
        float mo = __shfl_xor_sync(0xFFFFFFFFu, m, o);
        float so = __shfl_xor_sync(0xFFFFFFFFu, s, o);
        float M = fmaxf(m, mo);
        s = s * __expf(m - M) + so * __expf(mo - M);
        m = M;
    }
    if ((tid & 31) == 0) { redm[tid >> 5] = m; reds[tid >> 5] = s; }
    __syncthreads();
    if (tid == 0) {
        float M = redm[0], S = reds[0];
#pragma unroll
        for (int i = 1; i < 16; i++) {
            float M2 = fmaxf(M, redm[i]);
            S = S * __expf(M - M2) + reds[i] * __expf(redm[i] - M2);
            M = M2;
        }
        bcast = M + logf(S);
    }
    __syncthreads();
    const float lse = bcast;
    for (int k = tid; k < VOCAB / 4; k += 512) {
        float4 v = row4[k];
        v.x -= lse; v.y -= lse; v.z -= lse; v.w -= lse;
        row4[k] = v;
    }
}

// ---------------- launch ----------------
extern "C" void kernel_launch(void* const* d_in, const int* in_sizes, int n_in,
                              void* d_out, int out_size) {
    (void)in_sizes; (void)n_in; (void)out_size;
    const int*   x   = (const int*)d_in[0];
    const float* emb = (const float*)d_in[1];
    const float* Wi[3] = {(const float*)d_in[2], (const float*)d_in[5], (const float*)d_in[8]};
    const float* Wh[3] = {(const float*)d_in[3], (const float*)d_in[6], (const float*)d_in[9]};
    const float* bs[3] = {(const float*)d_in[4], (const float*)d_in[7], (const float*)d_in[10]};
    const float* fcW = (const float*)d_in[11];
    const float* fcb = (const float*)d_in[12];
    float* out = (float*)d_out;

    float *xg;
    __nv_bfloat16 *hb, *wb, *wib0, *wib1, *wib2;
    cudaGetSymbolAddress((void**)&xg,   g_xg);
    cudaGetSymbolAddress((void**)&hb,   g_hb);
    cudaGetSymbolAddress((void**)&wb,   g_wb);
    cudaGetSymbolAddress((void**)&wib0, g_wib0);
    cudaGetSymbolAddress((void**)&wib1, g_wib1);
    cudaGetSymbolAddress((void**)&wib2, g_wib2);

    cudaFuncSetAttribute(gemm_bf16, cudaFuncAttributeMaxDynamicSharedMemorySize, MMA_SMEM_BYTES);
    cudaFuncSetAttribute(lstm_rec_mma, cudaFuncAttributeMaxDynamicSharedMemorySize, REC_SMEM);

    // ncu -s 5 lands on lstm_rec_mma (layer 1)
    embed_bf<<<(NT * 256 + 255) / 256, 256>>>(x, emb, hb);                                    // 0
    cast_all<<<(VOCAB * 256 + 255) / 256, 256>>>(Wi[0], Wi[1], Wi[2], fcW,
                                                 wib0, wib1, wib2, wb);                       // 1

    gemm_bf16<<<dim3(NT/128, G4/128), 256, MMA_SMEM_BYTES>>>(hb, wib0, bs[0], xg, G4);        // 2
    lstm_rec_mma<<<8, 256, REC_SMEM>>>(xg, Wh[0], hb);                                        // 3

    gemm_bf16<<<dim3(NT/128, G4/128), 256, MMA_SMEM_BYTES>>>(hb, wib1, bs[1], xg, G4);        // 4
    lstm_rec_mma<<<8, 256, REC_SMEM>>>(xg, Wh[1], hb);                                        // 5 <- ncu

    gemm_bf16<<<dim3(NT/128, G4/128), 256, MMA_SMEM_BYTES>>>(hb, wib2, bs[2], xg, G4);        // 6
    lstm_rec_mma<<<8, 256, REC_SMEM>>>(xg, Wh[2], hb);                                        // 7

    gemm_bf16<<<dim3(NT/128, VOCAB/128), 256, MMA_SMEM_BYTES>>>(hb, wb, fcb, out, VOCAB);     // 8
    logsoftmax_kernel<<<NT, 512>>>(out);                                                      // 9
}

// round 11
// speedup vs baseline: 1.0017x; 1.0017x over previous
#include <cuda_runtime.h>
#include <cuda_bf16.h>
#include <cstdint>
#include <math.h>

#define BATCH 16
#define SEQT  256
#define VOCAB 32000
#define EMBD  200
#define HID   256
#define NT    (BATCH*SEQT)   // 4096 rows
#define G4    (4*HID)        // 1024 gate rows

// ---------------- scratch (static device arrays; no allocation) ----------------
__device__ float g_xg[NT*G4];                               // input projections (fp32)
__device__ __align__(16) __nv_bfloat16 g_hb[NT*HID];        // bf16 activations (layer I/O)
__device__ __align__(16) __nv_bfloat16 g_wb[VOCAB*HID];     // bf16 fcW
__device__ __align__(16) __nv_bfloat16 g_wib0[G4*HID];      // bf16 Wi0 (padded K 200->256)
__device__ __align__(16) __nv_bfloat16 g_wib1[G4*HID];      // bf16 Wi1
__device__ __align__(16) __nv_bfloat16 g_wib2[G4*HID];      // bf16 Wi2

// ---------------- helpers ----------------
__device__ __forceinline__ float sigmoid_f(float x) {
    x = fminf(fmaxf(x, -30.f), 30.f);
    return 1.f / (1.f + __expf(-x));
}
__device__ __forceinline__ float tanh_f(float x) {
    x = fminf(fmaxf(x, -15.f), 15.f);
    float e = __expf(2.f * x);
    return (e - 1.f) / (e + 1.f);
}
__device__ __forceinline__ uint32_t smem_u32(const void* p) {
    uint32_t a;
    asm("{ .reg .u64 t; cvta.to.shared.u64 t, %1; cvt.u32.u64 %0, t; }" : "=r"(a) : "l"(p));
    return a;
}

// ---------------- embedding gather -> bf16, padded to 256 cols ----------------
__global__ void embed_bf(const int* __restrict__ x, const float* __restrict__ emb,
                         __nv_bfloat16* __restrict__ out) {
    int idx = blockIdx.x * blockDim.x + threadIdx.x;
    if (idx < NT * 256) {
        int n = idx >> 8, e = idx & 255;
        float v = (e < EMBD) ? emb[(size_t)x[n] * EMBD + e] : 0.f;
        out[idx] = __float2bfloat16(v);
    }
}

// ---------------- one launch: cast fcW + all three Wi (Wi0 padded 200->256) ----------------
__global__ void cast_all(const float* __restrict__ Wi0, const float* __restrict__ Wi1,
                         const float* __restrict__ Wi2, const float* __restrict__ fcW,
                         __nv_bfloat16* __restrict__ o0, __nv_bfloat16* __restrict__ o1,
                         __nv_bfloat16* __restrict__ o2, __nv_bfloat16* __restrict__ ow) {
    int idx = blockIdx.x * blockDim.x + threadIdx.x;
    if (idx < VOCAB * 256) ow[idx] = __float2bfloat16(fcW[idx]);
    if (idx < G4 * 256) {
        int r = idx >> 8, c = idx & 255;
        o0[idx] = __float2bfloat16(c < EMBD ? Wi0[(size_t)r * EMBD + c] : 0.f);
        o1[idx] = __float2bfloat16(Wi1[idx]);
        o2[idx] = __float2bfloat16(Wi2[idx]);
    }
}

// ---------------- mma/ldmatrix primitives ----------------
__device__ __forceinline__ void ldsm_x4(uint32_t addr, uint32_t& r0, uint32_t& r1,
                                        uint32_t& r2, uint32_t& r3) {
    asm volatile("ldmatrix.sync.aligned.m8n8.x4.shared.b16 {%0,%1,%2,%3}, [%4];"
                 : "=r"(r0), "=r"(r1), "=r"(r2), "=r"(r3) : "r"(addr));
}
__device__ __forceinline__ void mma16816(float* c, const uint32_t* a, const uint32_t* b) {
    asm volatile("mma.sync.aligned.m16n8k16.row.col.f32.bf16.bf16.f32 "
                 "{%0,%1,%2,%3}, {%4,%5,%6,%7}, {%8,%9}, {%0,%1,%2,%3};"
                 : "+f"(c[0]), "+f"(c[1]), "+f"(c[2]), "+f"(c[3])
                 : "r"(a[0]), "r"(a[1]), "r"(a[2]), "r"(a[3]), "r"(b[0]), "r"(b[1]));
}

// ---------------- bf16 GEMM via warp mma.sync: out[M,N] = A @ B^T + bias ----------------
#define MMA_SMEM_BYTES (128*512*2)

__global__ __launch_bounds__(256, 1) void gemm_bf16(
    const __nv_bfloat16* __restrict__ Ab,
    const __nv_bfloat16* __restrict__ Bb,
    const float* __restrict__ bias,
    float* __restrict__ out,
    int Ncols)
{
    extern __shared__ __align__(128) unsigned char smem[];
    const uint32_t sbase = smem_u32(smem);
    const uint32_t sA = sbase;
    const uint32_t sB = sbase + 65536;

    const int tid = threadIdx.x;
    const int wid = tid >> 5;
    const int lid = tid & 31;
    const int row0 = blockIdx.x * 128;
    const int col0 = blockIdx.y * 128;

#pragma unroll
    for (int i = 0; i < 16; i++) {
        int idx = tid + i * 256;
        int r = idx >> 5, c = idx & 31;
        uint32_t soff = (uint32_t)r * 512u + (uint32_t)((c ^ (r & 7)) << 4);
        *(uint4*)(smem + soff) = *(const uint4*)(Ab + (size_t)(row0 + r) * HID + (c << 3));
        *(uint4*)(smem + 65536 + soff) = *(const uint4*)(Bb + (size_t)(col0 + r) * HID + (c << 3));
    }
    __syncthreads();

    const int mw = (wid & 1) * 64;
    const int nw = (wid >> 1) * 32;

    float c[4][4][4];
#pragma unroll
    for (int mi = 0; mi < 4; mi++)
#pragma unroll
        for (int ni = 0; ni < 4; ni++)
#pragma unroll
            for (int e = 0; e < 4; e++) c[mi][ni][e] = 0.f;

#pragma unroll
    for (int ks = 0; ks < 16; ks++) {
        uint32_t a[4][4];
#pragma unroll
        for (int mi = 0; mi < 4; mi++) {
            int r = mw + mi * 16 + (lid & 15);
            int chunk = ks * 2 + (lid >> 4);
            uint32_t addr = sA + (uint32_t)r * 512u + (uint32_t)((chunk ^ (r & 7)) << 4);
            ldsm_x4(addr, a[mi][0], a[mi][1], a[mi][2], a[mi][3]);
        }
        uint32_t b[4][2];
#pragma unroll
        for (int nb = 0; nb < 2; nb++) {
            int n = nw + nb * 16 + (lid & 7) + ((lid & 16) ? 8 : 0);
            int chunk = ks * 2 + ((lid & 8) ? 1 : 0);
            uint32_t addr = sB + (uint32_t)n * 512u + (uint32_t)((chunk ^ (n & 7)) << 4);
            uint32_t r0, r1, r2, r3;
            ldsm_x4(addr, r0, r1, r2, r3);
            b[nb * 2 + 0][0] = r0; b[nb * 2 + 0][1] = r1;
            b[nb * 2 + 1][0] = r2; b[nb * 2 + 1][1] = r3;
        }
#pragma unroll
        for (int mi = 0; mi < 4; mi++)
#pragma unroll
            for (int ni = 0; ni < 4; ni++)
                mma16816(c[mi][ni], a[mi], b[ni]);
    }

#pragma unroll
    for (int mi = 0; mi < 4; mi++) {
        int r = row0 + mw + mi * 16 + (lid >> 2);
#pragma unroll
        for (int ni = 0; ni < 4; ni++) {
            int col = col0 + nw + ni * 8 + (lid & 3) * 2;
            float2 bv = *(const float2*)&bias[col];
            float2 v0 = make_float2(c[mi][ni][0] + bv.x, c[mi][ni][1] + bv.y);
            float2 v1 = make_float2(c[mi][ni][2] + bv.x, c[mi][ni][3] + bv.y);
            *(float2*)&out[(size_t)r * Ncols + col] = v0;
            *(float2*)&out[(size_t)(r + 8) * Ncols + col] = v1;
        }
    }
}

// ---------------- LSTM recurrence: ONE 8-CTA cluster, all 16 batches, tensor-core gates ----
// CTA 'rank' owns hidden units j in [rank*32, rank*32+32) (gate rows q*256+rank*32+j).
// Per step: gates[128,16] = Whb[128,256] @ h[16,256]^T via mma.sync (A-frags preloaded in regs),
// activations on 256 threads, h slice (16x32 bf16, 80B pitch block = 1280B) bulk-copied to 7 peers.
#define SM_WHB   0                 // Whb [128][256] bf16, pitch 512B = 64KB
#define SM_HB    65536             // hB[2 bufs][8 kblocks][16 n][80B] = 2*10240
#define SM_GATES 86016             // gates [128][18] f32 = 9216
#define SM_MBAR  95232             // mbar[2]
#define REC_SMEM 95360

__global__ void __cluster_dims__(8, 1, 1) __launch_bounds__(256, 1)
lstm_rec_mma(const float* __restrict__ xg, const float* __restrict__ Wh,
             __nv_bfloat16* __restrict__ hout)
{
    extern __shared__ __align__(128) unsigned char smem[];
    uint32_t rank;
    asm("mov.u32 %0, %%cluster_ctarank;" : "=r"(rank));
    const int tid = threadIdx.x;
    const int wid = tid >> 5;
    const int lid = tid & 31;
    const uint32_t sbase = smem_u32(smem);
    const uint32_t sWhb = sbase + SM_WHB;
    const uint32_t sHB  = sbase + SM_HB;
    float* gatesF = (float*)(smem + SM_GATES);
    const uint32_t mbar_base = sbase + SM_MBAR;

    // ---- load Whb: local row lr=q*32+j <- global gate row q*256+rank*32+j, bf16 cast
    for (int i = tid; i < 128 * 64; i += 256) {
        int lr = i >> 6, cc = (i & 63) << 2;       // cc: col in floats (multiple of 4)
        int q = lr >> 5, j = lr & 31;
        float4 v = *(const float4*)&Wh[(size_t)(q * 256 + (int)rank * 32 + j) * 256 + cc];
        __nv_bfloat162 p0 = __floats2bfloat162_rn(v.x, v.y);
        __nv_bfloat162 p1 = __floats2bfloat162_rn(v.z, v.w);
        *(uint2*)(smem + SM_WHB + lr * 512 + cc * 2) =
            make_uint2(*(uint32_t*)&p0, *(uint32_t*)&p1);
    }
    // zero both h buffers
    for (int i = tid; i < (2 * 10240) / 4; i += 256)
        ((uint32_t*)(smem + SM_HB))[i] = 0u;
    if (tid == 0) {
        asm volatile("mbarrier.init.shared.b64 [%0], %1;" :: "r"(mbar_base), "r"(1u) : "memory");
        asm volatile("mbarrier.init.shared.b64 [%0], %1;" :: "r"(mbar_base + 8), "r"(1u) : "memory");
        asm volatile("mbarrier.arrive.expect_tx.shared.b64 _, [%0], %1;" :: "r"(mbar_base), "r"(8960u) : "memory");
        asm volatile("mbarrier.arrive.expect_tx.shared.b64 _, [%0], %1;" :: "r"(mbar_base + 8), "r"(8960u) : "memory");
    }
    __syncthreads();

    // ---- preload A fragments (warp w owns local rows [16w,16w+16), all 16 k-steps)
    uint32_t a[16][4];
#pragma unroll
    for (int ks = 0; ks < 16; ks++) {
        uint32_t addr = sWhb + (uint32_t)((wid << 4) + (lid & 15)) * 512u
                      + (uint32_t)ks * 32u + (uint32_t)((lid >> 4) << 4);
        ldsm_x4(addr, a[ks][0], a[ks][1], a[ks][2], a[ks][3]);
    }

    // one-time cluster barrier: peers' smem init (zeros + armed mbars) visible
    asm volatile("barrier.cluster.arrive.aligned;" ::: "memory");
    asm volatile("barrier.cluster.wait.aligned;" ::: "memory");

    const int j = tid & 31;          // hidden-local
    const int bp = tid >> 5;         // batch pair 0..7
    const int b0 = bp * 2, b1 = b0 + 1;
    float cst0 = 0.f, cst1 = 0.f;    // cell state (fp32, persistent)
    int ph0 = 0, ph1 = 0;

    const uint32_t nsel  = (uint32_t)((lid & 7) + ((lid & 16) ? 8 : 0));
    const uint32_t oct16 = (uint32_t)((lid & 8) ? 16 : 0);

    for (int t = 0; t < SEQT; t++) {
        // prefetch xg for this step (before the wait)
        float xgv0[4], xgv1[4];
#pragma unroll
        for (int q = 0; q < 4; q++) {
            size_t base = ((size_t)(b0 * 256 + t)) * 1024 + q * 256 + rank * 32 + j;
            xgv0[q] = __ldg(&xg[base]);
            xgv1[q] = __ldg(&xg[base + 256 * 1024]);
        }

        const int cb = t & 1;
        if (t > 0) {
            uint32_t mb = mbar_base + (uint32_t)cb * 8u;
            uint32_t par = cb ? ph1 : ph0;
            uint32_t done;
            asm volatile(
                "{\n\t.reg .pred p;\n\t"
                "mbarrier.try_wait.parity.acquire.cluster.shared::cta.b64 p, [%1], %2;\n\t"
                "selp.b32 %0, 1, 0, p;\n\t}"
                : "=r"(done) : "r"(mb), "r"(par) : "memory");
            if (!done) {
                asm volatile(
                    "{\n\t.reg .pred P1;\n\t"
                    "WL_%=: mbarrier.try_wait.parity.acquire.cluster.shared::cta.b64 P1, [%0], %1, 0x989680;\n\t"
                    "@P1 bra.uni WD_%=;\n\tbra.uni WL_%=;\n\tWD_%=:\n\t}"
                    :: "r"(mb), "r"(par) : "memory");
            }
            if (cb) ph1 ^= 1; else ph0 ^= 1;
            if (tid == 0) {   // re-arm for t+2 (safe: peers' next send requires our send below)
                asm volatile("mbarrier.arrive.expect_tx.shared.b64 _, [%0], %1;"
                             :: "r"(mb), "r"(8960u) : "memory");
            }
        }

        // ---- gates = Whb @ h^T  (per warp: 16 rows x 16 batches, K=256)
        float cf0[4] = {0.f, 0.f, 0.f, 0.f};
        float cf1[4] = {0.f, 0.f, 0.f, 0.f};
        const uint32_t hbuf = sHB + (uint32_t)cb * 10240u;
#pragma unroll
        for (int ks = 0; ks < 16; ks++) {
            uint32_t baddr = hbuf + (uint32_t)(ks >> 1) * 1280u + nsel * 80u
                           + (uint32_t)((ks & 1) * 32) + oct16;
            uint32_t r0, r1, r2, r3;
            ldsm_x4(baddr, r0, r1, r2, r3);
            uint32_t bA[2] = {r0, r1};
            uint32_t bB[2] = {r2, r3};
            mma16816(cf0, a[ks], bA);
            mma16816(cf1, a[ks], bB);
        }
        {
            int r = (wid << 4) + (lid >> 2);
            int col = (lid & 3) * 2;
            *(float2*)&gatesF[(size_t)r * 18 + col]           = make_float2(cf0[0], cf0[1]);
            *(float2*)&gatesF[(size_t)(r + 8) * 18 + col]     = make_float2(cf0[2], cf0[3]);
            *(float2*)&gatesF[(size_t)r * 18 + 8 + col]       = make_float2(cf1[0], cf1[1]);
            *(float2*)&gatesF[(size_t)(r + 8) * 18 + 8 + col] = make_float2(cf1[2], cf1[3]);
        }
        __syncthreads();

        // ---- activations: thread -> (hidden j, batches b0,b1)
        float2 gi = *(float2*)&gatesF[(size_t)(0 * 32 + j) * 18 + b0];
        float2 gf = *(float2*)&gatesF[(size_t)(1 * 32 + j) * 18 + b0];
        float2 gg = *(float2*)&gatesF[(size_t)(2 * 32 + j) * 18 + b0];
        float2 go = *(float2*)&gatesF[(size_t)(3 * 32 + j) * 18 + b0];
        float i0 = sigmoid_f(gi.x + xgv0[0]), i1 = sigmoid_f(gi.y + xgv1[0]);
        float f0 = sigmoid_f(gf.x + xgv0[1]), f1 = sigmoid_f(gf.y + xgv1[1]);
        float g0 = tanh_f   (gg.x + xgv0[2]), g1 = tanh_f   (gg.y + xgv1[2]);
        float o0 = sigmoid_f(go.x + xgv0[3]), o1 = sigmoid_f(go.y + xgv1[3]);
        cst0 = f0 * cst0 + i0 * g0;
        cst1 = f1 * cst1 + i1 * g1;
        float h0 = o0 * tanh_f(cst0);
        float h1 = o1 * tanh_f(cst1);

        const int nb = (t + 1) & 1;
        __nv_bfloat16 hb0 = __float2bfloat16(h0);
        __nv_bfloat16 hb1 = __float2bfloat16(h1);
        {   // local h block write: hB[nb][rank][b][j], row pitch 80B (40 bf16)
            __nv_bfloat16* hrow = (__nv_bfloat16*)(smem + SM_HB + nb * 10240 + rank * 1280);
            hrow[b0 * 40 + j] = hb0;
            hrow[b1 * 40 + j] = hb1;
        }
        __syncthreads();   // h block complete + STS drained

        if (t + 1 < SEQT && tid < 8 && tid != (int)rank) {
            asm volatile("fence.proxy.async.shared::cta;" ::: "memory");
            uint32_t src = sHB + (uint32_t)nb * 10240u + rank * 1280u;
            uint32_t lbar = mbar_base + (uint32_t)nb * 8u;
            uint32_t dst, rbar;
            asm("mapa.shared::cluster.u32 %0, %1, %2;" : "=r"(dst) : "r"(src), "r"(tid));
            asm("mapa.shared::cluster.u32 %0, %1, %2;" : "=r"(rbar) : "r"(lbar), "r"(tid));
            asm volatile(
                "cp.async.bulk.shared::cluster.shared::cta.mbarrier::complete_tx::bytes "
                "[%0], [%1], %2, [%3];"
                :: "r"(dst), "r"(src), "r"(1280u), "r"(rbar) : "memory");
        }

        // global h store AFTER the notify (off the critical path)
        hout[(size_t)(b0 * 256 + t) * 256 + rank * 32 + j] = hb0;
        hout[(size_t)(b1 * 256 + t) * 256 + rank * 32 + j] = hb1;
    }
}

// ---------------- online log_softmax (512 threads, float4) ----------------
__global__ __launch_bounds__(512) void logsoftmax_kernel(float* __restrict__ out) {
    const int n = blockIdx.x;
    float4* row4 = (float4*)(out + (size_t)n * VOCAB);
    const int tid = threadIdx.x;
    __shared__ float redm[16], reds[16];
    __shared__ float bcast;

    float m = -1e30f, s = 0.f;
    for (int k = tid; k < VOCAB / 4; k += 512) {
        float4 v = row4[k];
        float vm = fmaxf(fmaxf(v.x, v.y), fmaxf(v.z, v.w));
        float M = fmaxf(m, vm);
        float sc = __expf(m - M);
        s = s * sc + __expf(v.x - M) + __expf(v.y - M) + __expf(v.z - M) + __expf(v.w - M);
        m = M;
    }
#pragma unroll
    for (int o = 16; o; o >>= 1) {
        float mo = __shfl_xor_sync(0xFFFFFFFFu, m, o);
        float so = __shfl_xor_sync(0xFFFFFFFFu, s, o);
        float M = fmaxf(m, mo);
        s = s * __expf(m - M) + so * __expf(mo - M);
        m = M;
    }
    if ((tid & 31) == 0) { redm[tid >> 5] = m; reds[tid >> 5] = s; }
    __syncthreads();
    if (tid == 0) {
        float M = redm[0], S = reds[0];
#pragma unroll
        for (int i = 1; i < 16; i++) {
            float M2 = fmaxf(M, redm[i]);
            S = S * __expf(M - M2) + reds[i] * __expf(redm[i] - M2);
            M = M2;
        }
        bcast = M + logf(S);
    }
    __syncthreads();
    const float lse = bcast;
    for (int k = tid; k < VOCAB / 4; k += 512) {
        float4 v = row4[k];
        v.x -= lse; v.y -= lse; v.z -= lse; v.w -= lse;
        row4[k] = v;
    }
}

// ---------------- launch ----------------
extern "C" void kernel_launch(void* const* d_in, const int* in_sizes, int n_in,
                              void* d_out, int out_size) {
    (void)in_sizes; (void)n_in; (void)out_size;
    const int*   x   = (const int*)d_in[0];
    const float* emb = (const float*)d_in[1];
    const float* Wi[3] = {(const float*)d_in[2], (const float*)d_in[5], (const float*)d_in[8]};
    const float* Wh[3] = {(const float*)d_in[3], (const float*)d_in[6], (const float*)d_in[9]};
    const float* bs[3] = {(const float*)d_in[4], (const float*)d_in[7], (const float*)d_in[10]};
    const float* fcW = (const float*)d_in[11];
    const float* fcb = (const float*)d_in[12];
    float* out = (float*)d_out;

    float *xg;
    __nv_bfloat16 *hb, *wb, *wib0, *wib1, *wib2;
    cudaGetSymbolAddress((void**)&xg,   g_xg);
    cudaGetSymbolAddress((void**)&hb,   g_hb);
    cudaGetSymbolAddress((void**)&wb,   g_wb);
    cudaGetSymbolAddress((void**)&wib0, g_wib0);
    cudaGetSymbolAddress((void**)&wib1, g_wib1);
    cudaGetSymbolAddress((void**)&wib2, g_wib2);

    cudaFuncSetAttribute(gemm_bf16, cudaFuncAttributeMaxDynamicSharedMemorySize, MMA_SMEM_BYTES);
    cudaFuncSetAttribute(lstm_rec_mma, cudaFuncAttributeMaxDynamicSharedMemorySize, REC_SMEM);

    // ncu -s 5 lands on lstm_rec_mma (layer 1)
    embed_bf<<<(NT * 256 + 255) / 256, 256>>>(x, emb, hb);                                    // 0
    cast_all<<<(VOCAB * 256 + 255) / 256, 256>>>(Wi[0], Wi[1], Wi[2], fcW,
                                                 wib0, wib1, wib2, wb);                       // 1

    gemm_bf16<<<dim3(NT/128, G4/128), 256, MMA_SMEM_BYTES>>>(hb, wib0, bs[0], xg, G4);        // 2
    lstm_rec_mma<<<8, 256, REC_SMEM>>>(xg, Wh[0], hb);                                        // 3

    gemm_bf16<<<dim3(NT/128, G4/128), 256, MMA_SMEM_BYTES>>>(hb, wib1, bs[1], xg, G4);        // 4
    lstm_rec_mma<<<8, 256, REC_SMEM>>>(xg, Wh[1], hb);                                        // 5 <- ncu

    gemm_bf16<<<dim3(NT/128, G4/128), 256, MMA_SMEM_BYTES>>>(hb, wib2, bs[2], xg, G4);        // 6
    lstm_rec_mma<<<8, 256, REC_SMEM>>>(xg, Wh[2], hb);                                        // 7

    gemm_bf16<<<dim3(NT/128, VOCAB/128), 256, MMA_SMEM_BYTES>>>(hb, wb, fcb, out, VOCAB);     // 8
    logsoftmax_kernel<<<NT, 512>>>(out);                                                      // 9
}